// round 15
// baseline (speedup 1.0000x reference)
#include <cuda_runtime.h>
#include <cuda_fp16.h>
#include <cstdint>
#include <cstddef>

// ---------------- static device buffers (no runtime allocation) ----------------
// Unduplicated fp16 activation planes, chunk-major pre-swizzled: [k/32][4096 rows][64B]
__device__ __align__(256) __half g_X[4096 * 512];    // layer-0 input (16 chunks)
__device__ __align__(256) __half g_H1[4096 * 1024];  // hidden 1 (32 chunks)
__device__ __align__(256) __half g_H2[4096 * 1024];  // hidden 2 (32 chunks)
// W plane (single fp16), chunk-major pre-swizzled per layer:
// L0 @ 0 (4M el), L1 @ 4M (8M el), L2 @ 12M (4M el)
__device__ __align__(256) __half g_Wh[16 * 1024 * 1024];
// scheduler state (reset via cudaMemsetAsync each call):
// [0]=ticket head, [1]=ready alloc, [2..385]=ready entries (tile_id+1),
// [386..417]=L0 row flags, [418..449]=L1 row flags
__device__ int g_sched[450];

// ---------------- helpers ----------------
__device__ __forceinline__ uint32_t smem_u32(const void* p) {
    uint32_t a;
    asm("{ .reg .u64 t; cvta.to.shared.u64 t, %1; cvt.u32.u64 %0, t; }" : "=r"(a) : "l"(p));
    return a;
}

#define MBAR_INIT(a, c) asm volatile("mbarrier.init.shared.b64 [%0], %1;" ::"r"(a), "r"(c) : "memory")
#define MBAR_EXPECT(a, n) \
    asm volatile("mbarrier.arrive.expect_tx.shared.b64 _, [%0], %1;" ::"r"(a), "r"(n) : "memory")
#define MBAR_ARRIVE(a) \
    asm volatile("mbarrier.arrive.release.cta.shared::cta.b64 _, [%0];" ::"r"(a) : "memory")
#define FENCE_ASYNC() asm volatile("fence.proxy.async.shared::cta;" ::: "memory")
#define CP_BULK(dst, src, bytes, mbar)                                                        \
    asm volatile(                                                                             \
        "cp.async.bulk.shared::cluster.global.mbarrier::complete_tx::bytes [%0], [%1], %2, [%3];" \
        ::"r"(dst), "l"(src), "r"(bytes), "r"(mbar) : "memory")
#define MBAR_WAIT(a, ph)                                                                           \
    do {                                                                                           \
        uint32_t _m = (a), _p = (ph), _d;                                                          \
        asm volatile(                                                                              \
            "{\n\t.reg .pred p;\n\t"                                                               \
            "mbarrier.try_wait.parity.acquire.cta.shared::cta.b64 p, [%1], %2;\n\t"                \
            "selp.b32 %0,1,0,p;\n\t}"                                                              \
            : "=r"(_d) : "r"(_m), "r"(_p) : "memory");                                             \
        if (!_d) {                                                                                 \
            asm volatile(                                                                          \
                "{\n\t.reg .pred P1;\n\t"                                                          \
                "WL%=:\n\t"                                                                        \
                "mbarrier.try_wait.parity.acquire.cta.shared::cta.b64 P1, [%0], %1, 0x989680;\n\t" \
                "@P1 bra.uni WD%=;\n\t"                                                            \
                "bra.uni WL%=;\n\t"                                                                \
                "WD%=:\n\t}" ::"r"(_m), "r"(_p) : "memory");                                       \
        }                                                                                          \
    } while (0)

__device__ __forceinline__ void ldsm4(uint32_t& r0, uint32_t& r1, uint32_t& r2, uint32_t& r3,
                                      uint32_t addr) {
    asm volatile("ldmatrix.sync.aligned.m8n8.x4.shared.b16 {%0,%1,%2,%3}, [%4];"
                 : "=r"(r0), "=r"(r1), "=r"(r2), "=r"(r3) : "r"(addr));
}

__device__ __forceinline__ void mma16816(float* c, const uint32_t* a, const uint32_t* b) {
    asm volatile(
        "mma.sync.aligned.m16n8k16.row.col.f32.f16.f16.f32 "
        "{%0,%1,%2,%3}, {%4,%5,%6,%7}, {%8,%9}, {%0,%1,%2,%3};"
        : "+f"(c[0]), "+f"(c[1]), "+f"(c[2]), "+f"(c[3])
        : "r"(a[0]), "r"(a[1]), "r"(a[2]), "r"(a[3]), "r"(b[0]), "r"(b[1]));
}

__device__ __forceinline__ uint32_t pkh2(float a, float b) {
    __half2 t = __floats2half2_rn(a, b);
    return *(uint32_t*)&t;
}

// in-tile swizzle: row*64 + ((seg ^ ((row>>1)&3))<<4)  (seg = 16B segment 0..3)
#define SWZ(row, seg) ((uint32_t)((row) * 64 + ((((seg) ^ (((row) >> 1) & 3))) << 4)))

// ---------------- weight convert (single fp16) into chunk-major pre-swizzled layout ---------
template <int N, int K_IN>
__global__ void wconv(const float* __restrict__ W, __half* __restrict__ hi) {
    constexpr int SEGS = K_IN / 8;
    int t = blockIdx.x * blockDim.x + threadIdx.x;
    if (t >= 8 * N * SEGS) return;
    int s8 = t % SEGS;
    int n = (t / SEGS) % N;
    int e = t / (N * SEGS);
    int i = s8 * 8;
    const float* src = W + ((size_t)e * N + n) * K_IN + i;
    float4 v0 = *(const float4*)src;
    float4 v1 = *(const float4*)(src + 4);
    uint4 H;
    H.x = pkh2(v0.x, v0.y);
    H.y = pkh2(v0.z, v0.w);
    H.z = pkh2(v1.x, v1.y);
    H.w = pkh2(v1.z, v1.w);
    int kg = e * K_IN + i;
    int chunk = kg >> 5, seg = (kg >> 3) & 3;
    size_t off = (size_t)chunk * (N * 64) + SWZ(n, seg);  // bytes
    *(uint4*)((char*)hi + off) = H;
}

// ---------------- x convert (fp32 -> fp16, pre-swizzled chunk-major, NO blend) --------------
__global__ void xconv(const float* __restrict__ x, __half* __restrict__ Ah) {
    constexpr int SEGS = 64;  // 512/8
    int idx = blockIdx.x * blockDim.x + threadIdx.x;
    if (idx >= 4096 * SEGS) return;
    int b = idx >> 6, s8 = idx & 63;
    int i = s8 * 8;
    const float* src = x + (size_t)b * 512 + i;
    float4 v0 = *(const float4*)src;
    float4 v1 = *(const float4*)(src + 4);
    uint4 H;
    H.x = pkh2(v0.x, v0.y);
    H.y = pkh2(v0.z, v0.w);
    H.z = pkh2(v1.x, v1.y);
    H.w = pkh2(v1.z, v1.w);
    int chunk = i >> 5, seg = (i >> 3) & 3;
    size_t off = (size_t)chunk * (4096 * 64) + SWZ(b, seg);  // bytes
    *(uint4*)((char*)Ah + off) = H;
}

// ---------------- fused persistent 3-layer MLP, dependency-driven ready queue ---------------
// 640 uniform 128x128 tiles: L0 = [0,256), L1 = [256,512), L2 = [512,640).
// Tickets < 256 map directly to L0 tiles; tickets >= 256 consume ready[] entries that are
// published ONLY when all producer tiles of the needed row-block have completed.
__global__ __launch_bounds__(256, 2) void fused_mlp(
    const __half* __restrict__ ax, __half* __restrict__ h1, __half* __restrict__ h2,
    float* __restrict__ out, const __half* __restrict__ whAll,
    const float* __restrict__ blend, const float* __restrict__ B0,
    const float* __restrict__ B1, const float* __restrict__ B2) {
    constexpr int MT = 128, NT = 128, NST = 4;
    constexpr int AB = MT * 64, BB = NT * 64, STG = AB + BB;
    constexpr int MB_OFF = NST * STG;
    constexpr int RT_OFF = MB_OFF + 128;
    constexpr int TI_OFF = RT_OFF + MT * 8 * 4;
    constexpr int MW = 4, WNC = 64, NP = 4, NTT = 8;
    constexpr size_t CHA = 4096 * 64;

    extern __shared__ __align__(1024) char smem[];
    const uint32_t sb = smem_u32(smem);
    const int tid = threadIdx.x, wid = tid >> 5, lid = tid & 31;
    const int wm = wid % MW, wn = wid / MW;
    const uint32_t fullb = sb + MB_OFF;
    const uint32_t emptyb = sb + MB_OFF + 8 * NST;
    float* rtS = (float*)(smem + RT_OFF);
    int* tiS = (int*)(smem + TI_OFF);
    const int rl0 = lid >> 2;

    for (;;) {
        // ---- pop a ticket; resolve to a READY tile (entries appear only when inputs done) ----
        if (tid == 0) {
            int idx = atomicAdd(&g_sched[0], 1);
            int t;
            if (idx < 256) {
                t = idx;  // L0 tiles always ready
            } else if (idx < 640) {
                volatile int* e = (volatile int*)&g_sched[2 + (idx - 256)];
                int v;
                while ((v = *e) == 0) __nanosleep(128);
                __threadfence();  // acquire: order upstream stores before our TMA reads
                t = v - 1;
            } else {
                t = -1;
            }
            *tiS = t;
        }
        __syncthreads();
        const int t = *tiS;
        if (t < 0) return;

        // ---- decode tile ----
        int phase, local, NXv;
        if (t < 256) { phase = 0; local = t; NXv = 8; }
        else if (t < 512) { phase = 1; local = t - 256; NXv = 8; }
        else { phase = 2; local = t - 512; NXv = 4; }
        const int m = (NXv == 8) ? (local >> 3) : (local >> 2);
        const int n = (NXv == 8) ? (local & 7) : (local & 3);
        const int mBase = m * 128, nBase = n * 128;
        const int NCv = (phase == 0) ? 128 : 256;
        const int cpeMask = (phase == 0) ? 15 : 31;
        const int cpeShift = (phase == 0) ? 4 : 5;
        const __half* Ain = (phase == 0) ? ax : (phase == 1) ? h1 : h2;
        const __half* Wp = whAll + ((phase == 0) ? 0 : (phase == 1) ? 4194304 : 12582912);
        const float* Bp = (phase == 0) ? B0 : (phase == 1) ? B1 : B2;
        const int Nv = (phase == 2) ? 512 : 1024;
        const size_t CHBv = (size_t)Nv * 64;
        const bool elu = (phase < 2);
        char* outp = (phase == 0) ? (char*)h1 : (phase == 1) ? (char*)h2 : (char*)out;

        // ---- per-tile init: mbarriers + ratio table ----
        if (tid == 0) {
#pragma unroll
            for (int s = 0; s < NST; s++) {
                MBAR_INIT(fullb + 8 * s, 1);
                MBAR_INIT(emptyb + 8 * s, 8);
            }
            FENCE_ASYNC();
        }
        for (int i = tid; i < MT * 8; i += 256) {
            int r = i >> 3, e = i & 7;
            const float* bl = blend + (size_t)(mBase + r) * 8;
            rtS[i] = (e == 0) ? fmaxf(bl[7], 1e-30f)
                              : fmaxf(bl[e - 1], 1e-30f) / fmaxf(bl[e], 1e-30f);
        }
        __syncthreads();

        // ---- producer prologue (tid 0): prefetch NST chunks (inputs guaranteed ready) ----
        if (tid == 0) {
#pragma unroll
            for (int s = 0; s < NST; s++) {
                const uint32_t st = sb + s * STG;
                MBAR_EXPECT(fullb + 8 * s, STG);
                CP_BULK(st, (const char*)Ain + (size_t)(s & cpeMask) * CHA + (size_t)mBase * 64,
                        AB, fullb + 8 * s);
                CP_BULK(st + AB, (const char*)Wp + (size_t)s * CHBv + (size_t)nBase * 64,
                        BB, fullb + 8 * s);
            }
        }

        float acc[2][NTT][4];
#pragma unroll
        for (int a = 0; a < 2; a++)
#pragma unroll
            for (int b = 0; b < NTT; b++)
#pragma unroll
                for (int c = 0; c < 4; c++) acc[a][b][c] = 0.f;

        for (int c = 0; c < NCv; c++) {
            if (c > 0 && (c & cpeMask) == 0) {
                const int e = c >> cpeShift;
#pragma unroll
                for (int mt = 0; mt < 2; mt++)
#pragma unroll
                    for (int h = 0; h < 2; h++) {
                        int rloc = wm * 32 + mt * 16 + rl0 + h * 8;
                        float f = rtS[rloc * 8 + e];
#pragma unroll
                        for (int nt = 0; nt < NTT; nt++) {
                            acc[mt][nt][h * 2 + 0] *= f;
                            acc[mt][nt][h * 2 + 1] *= f;
                        }
                    }
            }
            const int s = c & (NST - 1);
            const int r = c / NST;
            MBAR_WAIT(fullb + 8 * s, r & 1);

            const uint32_t aB = sb + s * STG;
            const uint32_t bB = aB + AB;
            const int mat = lid >> 3, ri = lid & 7;
#pragma unroll
            for (int kk = 0; kk < 2; kk++) {
                uint32_t bh[NP][4];
#pragma unroll
                for (int p = 0; p < NP; p++) {
                    int nn = wn * WNC + p * 16 + ((mat >> 1) << 3) + ri;
                    int seg = kk * 2 + (mat & 1);
                    ldsm4(bh[p][0], bh[p][1], bh[p][2], bh[p][3], bB + SWZ(nn, seg));
                }
#pragma unroll
                for (int mt = 0; mt < 2; mt++) {
                    uint32_t ah[4];
                    int r2 = wm * 32 + mt * 16 + ((mat & 1) << 3) + ri;
                    int seg = kk * 2 + (mat >> 1);
                    ldsm4(ah[0], ah[1], ah[2], ah[3], aB + SWZ(r2, seg));
#pragma unroll
                    for (int nt = 0; nt < NTT; nt++) {
                        mma16816(acc[mt][nt], ah, &bh[nt >> 1][(nt & 1) * 2]);
                    }
                }
            }
            if (lid == 0) MBAR_ARRIVE(emptyb + 8 * s);
            if (tid == 0) {
                int cc = c + NST;
                if (cc < NCv) {
                    MBAR_WAIT(emptyb + 8 * s, r & 1);
                    const uint32_t st = sb + s * STG;
                    MBAR_EXPECT(fullb + 8 * s, STG);
                    CP_BULK(st, (const char*)Ain + (size_t)(cc & cpeMask) * CHA +
                                    (size_t)mBase * 64, AB, fullb + 8 * s);
                    CP_BULK(st + AB, (const char*)Wp + (size_t)cc * CHBv + (size_t)nBase * 64,
                            BB, fullb + 8 * s);
                }
            }
        }

        // final telescoping scale: acc *= bl'[7]
#pragma unroll
        for (int mt = 0; mt < 2; mt++)
#pragma unroll
            for (int h = 0; h < 2; h++) {
                int rloc = wm * 32 + mt * 16 + rl0 + h * 8;
                float f = rtS[rloc * 8 + 0];
#pragma unroll
                for (int nt = 0; nt < NTT; nt++) {
                    acc[mt][nt][h * 2 + 0] *= f;
                    acc[mt][nt][h * 2 + 1] *= f;
                }
            }

        __syncthreads();  // mainloop done; stage smem reusable

        // ---- epilogue: blended bias + optional ELU ----
        float* biasS = (float*)smem;
        for (int i = tid; i < 8 * NT; i += 256)
            biasS[i] = Bp[(i / NT) * Nv + nBase + (i % NT)];
        __syncthreads();

#pragma unroll
        for (int mt = 0; mt < 2; mt++) {
#pragma unroll
            for (int hh = 0; hh < 2; hh++) {
                const int row = mBase + wm * 32 + mt * 16 + rl0 + hh * 8;
                float4 b0 = *(const float4*)(blend + (size_t)row * 8);
                float4 b1 = *(const float4*)(blend + (size_t)row * 8 + 4);
                float blv[8] = {b0.x, b0.y, b0.z, b0.w, b1.x, b1.y, b1.z, b1.w};
#pragma unroll
                for (int nt = 0; nt < NTT; nt++) {
                    int cl = wn * WNC + nt * 8 + (lid & 3) * 2;
                    int col = nBase + cl;
                    float v0 = acc[mt][nt][hh * 2 + 0];
                    float v1 = acc[mt][nt][hh * 2 + 1];
                    float bb0 = 0.f, bb1 = 0.f;
#pragma unroll
                    for (int e = 0; e < 8; e++) {
                        bb0 += blv[e] * biasS[e * NT + cl];
                        bb1 += blv[e] * biasS[e * NT + cl + 1];
                    }
                    v0 += bb0;
                    v1 += bb1;
                    if (elu) {
                        v0 = (v0 > 0.f) ? v0 : expm1f(v0);
                        v1 = (v1 > 0.f) ? v1 : expm1f(v1);
                    }
                    if (phase < 2) {
                        size_t off = (size_t)(col >> 5) * CHA +
                                     (uint32_t)(SWZ(row, (col >> 3) & 3) + (col & 7) * 2);
                        *(uint32_t*)(outp + off) = pkh2(v0, v1);
                    } else {
                        *(float2*)((float*)outp + (size_t)row * Nv + col) = make_float2(v0, v1);
                    }
                }
            }
        }

        // ---- publish completion; last tile of a row-block pushes downstream ready entries ----
        __syncthreads();  // all threads' stores done before release
        if (tid == 0 && phase < 2) {
            __threadfence();  // release this CTA's stores (others ordered via syncthreads)
            int* flag = &g_sched[386 + phase * 32 + m];
            int old = atomicAdd(flag, 1);
            if (old == 7) {  // row-block m of this layer fully complete -> push children
                if (phase == 0) {
                    int pos = atomicAdd(&g_sched[1], 8);
#pragma unroll
                    for (int j = 0; j < 8; j++)
                        atomicExch(&g_sched[2 + pos + j], 256 + m * 8 + j + 1);
                } else {
                    int pos = atomicAdd(&g_sched[1], 4);
#pragma unroll
                    for (int j = 0; j < 4; j++)
                        atomicExch(&g_sched[2 + pos + j], 512 + m * 4 + j + 1);
                }
            }
        }
    }
}

// ---------------- host ----------------
extern "C" void kernel_launch(void* const* d_in, const int* in_sizes, int n_in,
                              void* d_out, int out_size) {
    const float* blend = (const float*)d_in[0];  // (4096, 8)
    const float* x     = (const float*)d_in[1];  // (4096, 512)
    const float* W0    = (const float*)d_in[2];  // (8, 1024, 512)
    const float* B0    = (const float*)d_in[3];
    const float* W1    = (const float*)d_in[4];  // (8, 1024, 1024)
    const float* B1    = (const float*)d_in[5];
    const float* W2    = (const float*)d_in[6];  // (8, 512, 1024)
    const float* B2    = (const float*)d_in[7];
    float* out = (float*)d_out;                  // (4096, 512)

    __half *ax, *h1, *h2, *wh;
    int* sc;
    cudaGetSymbolAddress((void**)&ax, g_X);
    cudaGetSymbolAddress((void**)&h1, g_H1);
    cudaGetSymbolAddress((void**)&h2, g_H2);
    cudaGetSymbolAddress((void**)&wh, g_Wh);
    cudaGetSymbolAddress((void**)&sc, g_sched);

    // reset scheduler state (graph-capturable async memset)
    cudaMemsetAsync(sc, 0, 450 * sizeof(int));

    // converts into chunk-major pre-swizzled layout (R11 versions)
    wconv<1024, 512><<<(8 * 1024 * 64 + 255) / 256, 256>>>(W0, wh);
    wconv<1024, 1024><<<(8 * 1024 * 128 + 255) / 256, 256>>>(W1, wh + 4194304);
    wconv<512, 1024><<<(8 * 512 * 128 + 255) / 256, 256>>>(W2, wh + 12582912);
    xconv<<<(4096 * 64 + 255) / 256, 256>>>(x, ax);

    // fused persistent kernel: 4-stage ring (64KB) + mbar + 4KB ratio + tile bcast
    constexpr int SMEM = 4 * (128 * 64 + 128 * 64) + 128 + 128 * 8 * 4 + 16;  // ~68.2KB
    cudaFuncSetAttribute(fused_mlp, cudaFuncAttributeMaxDynamicSharedMemorySize, SMEM);

    int nsm = 148;
    cudaDeviceGetAttribute(&nsm, cudaDevAttrMultiProcessorCount, 0);
    fused_mlp<<<2 * nsm, 256, SMEM>>>(ax, h1, h2, out, wh, blend, B0, B1, B2);
}

// round 16
// speedup vs baseline: 1.1902x; 1.1902x over previous
#include <cuda_runtime.h>
#include <cuda_fp16.h>
#include <cstdint>
#include <cstddef>

// ---------------- static device buffers (no runtime allocation) ----------------
// Unduplicated fp16 activation planes, chunk-major pre-swizzled: [k/32][4096 rows][64B]
__device__ __align__(256) __half g_X[4096 * 512];    // layer-0 input (16 chunks)
__device__ __align__(256) __half g_H1[4096 * 1024];  // hidden 1 (32 chunks)
__device__ __align__(256) __half g_H2[4096 * 1024];  // hidden 2 (32 chunks)
// W plane (single fp16), chunk-major pre-swizzled per layer:
// L0 @ 0 (4M el), L1 @ 4M (8M el), L2 @ 12M (4M el)
__device__ __align__(256) __half g_Wh[16 * 1024 * 1024];

// ---------------- helpers ----------------
__device__ __forceinline__ uint32_t smem_u32(const void* p) {
    uint32_t a;
    asm("{ .reg .u64 t; cvta.to.shared.u64 t, %1; cvt.u32.u64 %0, t; }" : "=r"(a) : "l"(p));
    return a;
}

#define MBAR_INIT(a, c) asm volatile("mbarrier.init.shared.b64 [%0], %1;" ::"r"(a), "r"(c) : "memory")
#define MBAR_EXPECT(a, n) \
    asm volatile("mbarrier.arrive.expect_tx.shared.b64 _, [%0], %1;" ::"r"(a), "r"(n) : "memory")
#define MBAR_ARRIVE(a) \
    asm volatile("mbarrier.arrive.release.cta.shared::cta.b64 _, [%0];" ::"r"(a) : "memory")
#define FENCE_ASYNC() asm volatile("fence.proxy.async.shared::cta;" ::: "memory")
#define CP_BULK(dst, src, bytes, mbar)                                                        \
    asm volatile(                                                                             \
        "cp.async.bulk.shared::cluster.global.mbarrier::complete_tx::bytes [%0], [%1], %2, [%3];" \
        ::"r"(dst), "l"(src), "r"(bytes), "r"(mbar) : "memory")
#define MBAR_WAIT(a, ph)                                                                           \
    do {                                                                                           \
        uint32_t _m = (a), _p = (ph), _d;                                                          \
        asm volatile(                                                                              \
            "{\n\t.reg .pred p;\n\t"                                                               \
            "mbarrier.try_wait.parity.acquire.cta.shared::cta.b64 p, [%1], %2;\n\t"                \
            "selp.b32 %0,1,0,p;\n\t}"                                                              \
            : "=r"(_d) : "r"(_m), "r"(_p) : "memory");                                             \
        if (!_d) {                                                                                 \
            asm volatile(                                                                          \
                "{\n\t.reg .pred P1;\n\t"                                                          \
                "WL%=:\n\t"                                                                        \
                "mbarrier.try_wait.parity.acquire.cta.shared::cta.b64 P1, [%0], %1, 0x989680;\n\t" \
                "@P1 bra.uni WD%=;\n\t"                                                            \
                "bra.uni WL%=;\n\t"                                                                \
                "WD%=:\n\t}" ::"r"(_m), "r"(_p) : "memory");                                       \
        }                                                                                          \
    } while (0)

__device__ __forceinline__ void ldsm4(uint32_t& r0, uint32_t& r1, uint32_t& r2, uint32_t& r3,
                                      uint32_t addr) {
    asm volatile("ldmatrix.sync.aligned.m8n8.x4.shared.b16 {%0,%1,%2,%3}, [%4];"
                 : "=r"(r0), "=r"(r1), "=r"(r2), "=r"(r3) : "r"(addr));
}

__device__ __forceinline__ void mma16816(float* c, const uint32_t* a, const uint32_t* b) {
    asm volatile(
        "mma.sync.aligned.m16n8k16.row.col.f32.f16.f16.f32 "
        "{%0,%1,%2,%3}, {%4,%5,%6,%7}, {%8,%9}, {%0,%1,%2,%3};"
        : "+f"(c[0]), "+f"(c[1]), "+f"(c[2]), "+f"(c[3])
        : "r"(a[0]), "r"(a[1]), "r"(a[2]), "r"(a[3]), "r"(b[0]), "r"(b[1]));
}

__device__ __forceinline__ uint32_t pkh2(float a, float b) {
    __half2 t = __floats2half2_rn(a, b);
    return *(uint32_t*)&t;
}

// in-tile swizzle: row*64 + ((seg ^ ((row>>1)&3))<<4)  (seg = 16B segment 0..3)
#define SWZ(row, seg) ((uint32_t)((row) * 64 + ((((seg) ^ (((row) >> 1) & 3))) << 4)))

// ---------------- weight convert (single fp16) into chunk-major pre-swizzled layout ---------
template <int N, int K_IN>
__global__ void wconv(const float* __restrict__ W, __half* __restrict__ hi) {
    constexpr int SEGS = K_IN / 8;
    int t = blockIdx.x * blockDim.x + threadIdx.x;
    if (t >= 8 * N * SEGS) return;
    int s8 = t % SEGS;
    int n = (t / SEGS) % N;
    int e = t / (N * SEGS);
    int i = s8 * 8;
    const float* src = W + ((size_t)e * N + n) * K_IN + i;
    float4 v0 = *(const float4*)src;
    float4 v1 = *(const float4*)(src + 4);
    uint4 H;
    H.x = pkh2(v0.x, v0.y);
    H.y = pkh2(v0.z, v0.w);
    H.z = pkh2(v1.x, v1.y);
    H.w = pkh2(v1.z, v1.w);
    int kg = e * K_IN + i;
    int chunk = kg >> 5, seg = (kg >> 3) & 3;
    size_t off = (size_t)chunk * (N * 64) + SWZ(n, seg);  // bytes
    *(uint4*)((char*)hi + off) = H;
}

// ---------------- x convert (fp32 -> fp16, pre-swizzled chunk-major, NO blend) --------------
__global__ void xconv(const float* __restrict__ x, __half* __restrict__ Ah) {
    constexpr int SEGS = 64;  // 512/8
    int idx = blockIdx.x * blockDim.x + threadIdx.x;
    if (idx >= 4096 * SEGS) return;
    int b = idx >> 6, s8 = idx & 63;
    int i = s8 * 8;
    const float* src = x + (size_t)b * 512 + i;
    float4 v0 = *(const float4*)src;
    float4 v1 = *(const float4*)(src + 4);
    uint4 H;
    H.x = pkh2(v0.x, v0.y);
    H.y = pkh2(v0.z, v0.w);
    H.z = pkh2(v1.x, v1.y);
    H.w = pkh2(v1.z, v1.w);
    int chunk = i >> 5, seg = (i >> 3) & 3;
    size_t off = (size_t)chunk * (4096 * 64) + SWZ(b, seg);  // bytes
    *(uint4*)((char*)Ah + off) = H;
}

// ---------------- GEMM: C(4096,N) = [blend ⊙ h](4096, 8*K_IN) x W^T ------------------------
// A plane is UNDUPLICATED plain-fp16 h. Blend via telescoping accumulator rescale.
// K-chunk = 64 (two 32-wide sub-planes per stage); NST=3 ring of 32KB stages; occ 2.
// OUTMODE: 0 = fp32 row-major out, 1 = fp16 pre-swizzled chunk-major plane (next layer).
template <int MT, int NT, int K_IN, int N, int OUTMODE, bool DO_ELU>
__global__ __launch_bounds__(256, 2) void gemm_mma(
    const __half* __restrict__ Ah, const __half* __restrict__ Wh,
    const float* __restrict__ blend, const float* __restrict__ Bias,
    void* __restrict__ outp) {
    constexpr int CPE = K_IN / 64;     // 64-chunks per expert
    constexpr int NC = 8 * CPE;        // total 64-chunks
    constexpr int NST = 3;
    constexpr int AB = MT * 64;        // bytes per A sub-tile (one 32-plane slice)
    constexpr int BB = NT * 64;        // bytes per B sub-tile
    constexpr int STG = 2 * AB + 2 * BB;
    constexpr int MB_OFF = NST * STG;  // full[s] at +8s, empty[s] at +8*NST+8s
    constexpr int RT_OFF = MB_OFF + 128;  // fp32 ratio table [MT][8]
    constexpr int MW = MT / 32;        // warps along M
    constexpr int WNC = NT * MW / 8;   // warp N extent
    constexpr int NP = WNC / 16;
    constexpr int NTT = WNC / 8;
    constexpr size_t CHA = 4096 * 64;  // bytes per 32-chunk A plane
    constexpr size_t CHB = (size_t)N * 64;

    extern __shared__ __align__(1024) char smem[];
    const uint32_t sb = smem_u32(smem);
    const int tid = threadIdx.x, wid = tid >> 5, lid = tid & 31;
    const int wm = wid % MW, wn = wid / MW;
    const int mBase = blockIdx.y * MT, nBase = blockIdx.x * NT;

    const uint32_t fullb = sb + MB_OFF;
    const uint32_t emptyb = sb + MB_OFF + 8 * NST;
    float* rtS = (float*)(smem + RT_OFF);

    if (tid == 0) {
#pragma unroll
        for (int s = 0; s < NST; s++) {
            MBAR_INIT(fullb + 8 * s, 1);
            MBAR_INIT(emptyb + 8 * s, 8);
        }
        FENCE_ASYNC();
    }
    // ratio table: rtS[r*8+e] = bl'[e-1]/bl'[e] (e>=1); rtS[r*8+0] = bl'[7] (final scale)
    for (int i = tid; i < MT * 8; i += 256) {
        int r = i >> 3, e = i & 7;
        const float* bl = blend + (size_t)(mBase + r) * 8;
        float v;
        if (e == 0) {
            v = fmaxf(bl[7], 1e-30f);
        } else {
            v = fmaxf(bl[e - 1], 1e-30f) / fmaxf(bl[e], 1e-30f);
        }
        rtS[i] = v;
    }
    __syncthreads();

    // issue one 64-chunk: A sub-planes 2c,2c+1 (mod expert) + W sub-planes 2c,2c+1 (global)
    auto issue = [&](int s, int c) {
        const uint32_t st = sb + s * STG;
        const uint32_t mb = fullb + 8 * s;
        const int al = (c % CPE) * 2;   // A 32-plane index within expert
        const int wg = c * 2;           // W 32-plane global index
        MBAR_EXPECT(mb, STG);
        CP_BULK(st,          (const char*)Ah + (size_t)(al + 0) * CHA + (size_t)mBase * 64, AB, mb);
        CP_BULK(st + AB,     (const char*)Ah + (size_t)(al + 1) * CHA + (size_t)mBase * 64, AB, mb);
        CP_BULK(st + 2 * AB,      (const char*)Wh + (size_t)(wg + 0) * CHB + (size_t)nBase * 64, BB, mb);
        CP_BULK(st + 2 * AB + BB, (const char*)Wh + (size_t)(wg + 1) * CHB + (size_t)nBase * 64, BB, mb);
    };

    if (tid == 0) {
#pragma unroll
        for (int s = 0; s < NST; s++) issue(s, s);
    }

    float acc[2][NTT][4];
#pragma unroll
    for (int a = 0; a < 2; a++)
#pragma unroll
        for (int b = 0; b < NTT; b++)
#pragma unroll
            for (int c = 0; c < 4; c++) acc[a][b][c] = 0.f;

    const int rl0 = (lid >> 2);  // base row-in-tile component

    for (int c = 0; c < NC; c++) {
        // expert boundary: rescale accumulators by bl[e-1]/bl[e] (per row, fp32)
        if (c > 0 && (c % CPE) == 0) {
            const int e = c / CPE;
#pragma unroll
            for (int mt = 0; mt < 2; mt++)
#pragma unroll
                for (int h = 0; h < 2; h++) {
                    int rloc = wm * 32 + mt * 16 + rl0 + h * 8;
                    float f = rtS[rloc * 8 + e];
#pragma unroll
                    for (int nt = 0; nt < NTT; nt++) {
                        acc[mt][nt][h * 2 + 0] *= f;
                        acc[mt][nt][h * 2 + 1] *= f;
                    }
                }
        }
        const int s = c % NST;
        const int r = c / NST;
        MBAR_WAIT(fullb + 8 * s, r & 1);

        const uint32_t st = sb + s * STG;
        const int mat = lid >> 3, ri = lid & 7;
#pragma unroll
        for (int sub = 0; sub < 2; sub++) {
            const uint32_t aB = st + sub * AB;
            const uint32_t bB = st + 2 * AB + sub * BB;
#pragma unroll
            for (int kk = 0; kk < 2; kk++) {
                uint32_t bh[NP][4];
#pragma unroll
                for (int p = 0; p < NP; p++) {
                    int n = wn * WNC + p * 16 + ((mat >> 1) << 3) + ri;
                    int seg = kk * 2 + (mat & 1);
                    ldsm4(bh[p][0], bh[p][1], bh[p][2], bh[p][3], bB + SWZ(n, seg));
                }
#pragma unroll
                for (int mt = 0; mt < 2; mt++) {
                    uint32_t ah[4];
                    int r2 = wm * 32 + mt * 16 + ((mat & 1) << 3) + ri;
                    int seg = kk * 2 + (mat >> 1);
                    ldsm4(ah[0], ah[1], ah[2], ah[3], aB + SWZ(r2, seg));
#pragma unroll
                    for (int nt = 0; nt < NTT; nt++) {
                        mma16816(acc[mt][nt], ah, &bh[nt >> 1][(nt & 1) * 2]);
                    }
                }
            }
        }
        if (lid == 0) MBAR_ARRIVE(emptyb + 8 * s);
        if (tid == 0) {
            int cc = c + NST;
            if (cc < NC) {
                MBAR_WAIT(emptyb + 8 * s, r & 1);
                issue(s, cc);
            }
        }
    }

    // final telescoping scale: acc *= bl'[7]
#pragma unroll
    for (int mt = 0; mt < 2; mt++)
#pragma unroll
        for (int h = 0; h < 2; h++) {
            int rloc = wm * 32 + mt * 16 + rl0 + h * 8;
            float f = rtS[rloc * 8 + 0];
#pragma unroll
            for (int nt = 0; nt < NTT; nt++) {
                acc[mt][nt][h * 2 + 0] *= f;
                acc[mt][nt][h * 2 + 1] *= f;
            }
        }

    __syncthreads();  // all warps out of mainloop; stage smem now dead

    // ---- epilogue: blended bias + optional ELU ----
    float* biasS = (float*)smem;  // reuse stage region
    for (int i = tid; i < 8 * NT; i += 256)
        biasS[i] = Bias[(i / NT) * N + nBase + (i % NT)];
    __syncthreads();

#pragma unroll
    for (int mt = 0; mt < 2; mt++) {
#pragma unroll
        for (int hh = 0; hh < 2; hh++) {
            const int row = mBase + wm * 32 + mt * 16 + rl0 + hh * 8;
            float4 b0 = *(const float4*)(blend + (size_t)row * 8);
            float4 b1 = *(const float4*)(blend + (size_t)row * 8 + 4);
            float blv[8] = {b0.x, b0.y, b0.z, b0.w, b1.x, b1.y, b1.z, b1.w};
#pragma unroll
            for (int nt = 0; nt < NTT; nt++) {
                int cl = wn * WNC + nt * 8 + (lid & 3) * 2;  // tile-local col
                int col = nBase + cl;                        // global col
                float v0 = acc[mt][nt][hh * 2 + 0];
                float v1 = acc[mt][nt][hh * 2 + 1];
                float bb0 = 0.f, bb1 = 0.f;
#pragma unroll
                for (int e = 0; e < 8; e++) {
                    bb0 += blv[e] * biasS[e * NT + cl];
                    bb1 += blv[e] * biasS[e * NT + cl + 1];
                }
                v0 += bb0;
                v1 += bb1;
                if (DO_ELU) {
                    v0 = (v0 > 0.f) ? v0 : expm1f(v0);
                    v1 = (v1 > 0.f) ? v1 : expm1f(v1);
                }
                if (OUTMODE == 1) {
                    // write fp16 h directly in pre-swizzled chunk-major plane layout
                    size_t off = (size_t)(col >> 5) * CHA +
                                 (uint32_t)(SWZ(row, (col >> 3) & 3) + (col & 7) * 2);
                    *(uint32_t*)((char*)outp + off) = pkh2(v0, v1);
                } else {
                    *(float2*)((float*)outp + (size_t)row * N + col) = make_float2(v0, v1);
                }
            }
        }
    }
}

// ---------------- host ----------------
extern "C" void kernel_launch(void* const* d_in, const int* in_sizes, int n_in,
                              void* d_out, int out_size) {
    const float* blend = (const float*)d_in[0];  // (4096, 8)
    const float* x     = (const float*)d_in[1];  // (4096, 512)
    const float* W0    = (const float*)d_in[2];  // (8, 1024, 512)
    const float* B0    = (const float*)d_in[3];
    const float* W1    = (const float*)d_in[4];  // (8, 1024, 1024)
    const float* B1    = (const float*)d_in[5];
    const float* W2    = (const float*)d_in[6];  // (8, 512, 1024)
    const float* B2    = (const float*)d_in[7];
    float* out = (float*)d_out;                  // (4096, 512)

    __half *ax, *h1, *h2, *wh;
    cudaGetSymbolAddress((void**)&ax, g_X);
    cudaGetSymbolAddress((void**)&h1, g_H1);
    cudaGetSymbolAddress((void**)&h2, g_H2);
    cudaGetSymbolAddress((void**)&wh, g_Wh);

    // converts into chunk-major pre-swizzled layout (R11 versions)
    wconv<1024, 512><<<(8 * 1024 * 64 + 255) / 256, 256>>>(W0, wh);
    wconv<1024, 1024><<<(8 * 1024 * 128 + 255) / 256, 256>>>(W1, wh + 4194304);
    wconv<512, 1024><<<(8 * 512 * 128 + 255) / 256, 256>>>(W2, wh + 12582912);
    xconv<<<(4096 * 64 + 255) / 256, 256>>>(x, ax);

    // layers 0/1: 3-stage ring of 32KB stages (96KB) + mbar + 4KB ratio table
    constexpr int S_L01 = 3 * (2 * 128 * 64 + 2 * 128 * 64) + 128 + 128 * 8 * 4;  // ~100.2KB
    // layer 2: 3-stage of 24KB stages (72KB) + mbar + 2KB ratio table
    constexpr int S_L2 = 3 * (2 * 64 * 64 + 2 * 128 * 64) + 128 + 64 * 8 * 4;     // ~74.2KB
    cudaFuncSetAttribute(gemm_mma<128, 128, 512, 1024, 1, true>,
                         cudaFuncAttributeMaxDynamicSharedMemorySize, S_L01);
    cudaFuncSetAttribute(gemm_mma<128, 128, 1024, 1024, 1, true>,
                         cudaFuncAttributeMaxDynamicSharedMemorySize, S_L01);
    cudaFuncSetAttribute(gemm_mma<64, 128, 1024, 512, 0, false>,
                         cudaFuncAttributeMaxDynamicSharedMemorySize, S_L2);

    // layer 0: x plane -> h1 plane (pre-swizzled fp16), ELU
    gemm_mma<128, 128, 512, 1024, 1, true><<<dim3(8, 32), 256, S_L01>>>(
        ax, wh, blend, B0, h1);
    // layer 1: h1 plane -> h2 plane, ELU
    gemm_mma<128, 128, 1024, 1024, 1, true><<<dim3(8, 32), 256, S_L01>>>(
        h1, wh + 4194304, blend, B1, h2);
    // layer 2: h2 plane -> fp32 out, linear
    gemm_mma<64, 128, 1024, 512, 0, false><<<dim3(4, 64), 256, S_L2>>>(
        h2, wh + 12582912, blend, B2, out);
}

// round 17
// speedup vs baseline: 1.2295x; 1.0330x over previous
#include <cuda_runtime.h>
#include <cuda_fp16.h>
#include <cstdint>
#include <cstddef>

// ---------------- static device buffers (no runtime allocation) ----------------
// Unduplicated fp16 activation planes, chunk-major pre-swizzled: [k/32][4096 rows][64B]
__device__ __align__(256) __half g_X[4096 * 512];    // layer-0 input (16 chunks)
__device__ __align__(256) __half g_H1[4096 * 1024];  // hidden 1 (32 chunks)
__device__ __align__(256) __half g_H2[4096 * 1024];  // hidden 2 (32 chunks)
// W plane (single fp16), chunk-major pre-swizzled per layer:
// L0 @ 0 (4M el), L1 @ 4M (8M el), L2 @ 12M (4M el)
__device__ __align__(256) __half g_Wh[16 * 1024 * 1024];

// ---------------- helpers ----------------
__device__ __forceinline__ uint32_t smem_u32(const void* p) {
    uint32_t a;
    asm("{ .reg .u64 t; cvta.to.shared.u64 t, %1; cvt.u32.u64 %0, t; }" : "=r"(a) : "l"(p));
    return a;
}

#define MBAR_INIT(a, c) asm volatile("mbarrier.init.shared.b64 [%0], %1;" ::"r"(a), "r"(c) : "memory")
#define MBAR_EXPECT(a, n) \
    asm volatile("mbarrier.arrive.expect_tx.shared.b64 _, [%0], %1;" ::"r"(a), "r"(n) : "memory")
#define MBAR_ARRIVE(a) \
    asm volatile("mbarrier.arrive.release.cta.shared::cta.b64 _, [%0];" ::"r"(a) : "memory")
#define FENCE_ASYNC() asm volatile("fence.proxy.async.shared::cta;" ::: "memory")
#define CP_BULK(dst, src, bytes, mbar)                                                        \
    asm volatile(                                                                             \
        "cp.async.bulk.shared::cluster.global.mbarrier::complete_tx::bytes [%0], [%1], %2, [%3];" \
        ::"r"(dst), "l"(src), "r"(bytes), "r"(mbar) : "memory")
#define MBAR_WAIT(a, ph)                                                                           \
    do {                                                                                           \
        uint32_t _m = (a), _p = (ph), _d;                                                          \
        asm volatile(                                                                              \
            "{\n\t.reg .pred p;\n\t"                                                               \
            "mbarrier.try_wait.parity.acquire.cta.shared::cta.b64 p, [%1], %2;\n\t"                \
            "selp.b32 %0,1,0,p;\n\t}"                                                              \
            : "=r"(_d) : "r"(_m), "r"(_p) : "memory");                                             \
        if (!_d) {                                                                                 \
            asm volatile(                                                                          \
                "{\n\t.reg .pred P1;\n\t"                                                          \
                "WL%=:\n\t"                                                                        \
                "mbarrier.try_wait.parity.acquire.cta.shared::cta.b64 P1, [%0], %1, 0x989680;\n\t" \
                "@P1 bra.uni WD%=;\n\t"                                                            \
                "bra.uni WL%=;\n\t"                                                                \
                "WD%=:\n\t}" ::"r"(_m), "r"(_p) : "memory");                                       \
        }                                                                                          \
    } while (0)

__device__ __forceinline__ void ldsm4(uint32_t& r0, uint32_t& r1, uint32_t& r2, uint32_t& r3,
                                      uint32_t addr) {
    asm volatile("ldmatrix.sync.aligned.m8n8.x4.shared.b16 {%0,%1,%2,%3}, [%4];"
                 : "=r"(r0), "=r"(r1), "=r"(r2), "=r"(r3) : "r"(addr));
}

__device__ __forceinline__ void mma16816(float* c, const uint32_t* a, const uint32_t* b) {
    asm volatile(
        "mma.sync.aligned.m16n8k16.row.col.f32.f16.f16.f32 "
        "{%0,%1,%2,%3}, {%4,%5,%6,%7}, {%8,%9}, {%0,%1,%2,%3};"
        : "+f"(c[0]), "+f"(c[1]), "+f"(c[2]), "+f"(c[3])
        : "r"(a[0]), "r"(a[1]), "r"(a[2]), "r"(a[3]), "r"(b[0]), "r"(b[1]));
}

__device__ __forceinline__ uint32_t pkh2(float a, float b) {
    __half2 t = __floats2half2_rn(a, b);
    return *(uint32_t*)&t;
}

// in-tile swizzle: row*64 + ((seg ^ ((row>>1)&3))<<4)  (seg = 16B segment 0..3)
#define SWZ(row, seg) ((uint32_t)((row) * 64 + ((((seg) ^ (((row) >> 1) & 3))) << 4)))

// ---------------- fused converter: x + W0 + W1 + W2 in one launch ---------------------------
// Work item = one 8-fp32 group -> one 16B fp16 write into pre-swizzled chunk-major layout.
// Regions (item counts): x: 256K | W0: 512K | W1: 1024K | W2: 512K  (total 2304K)
__device__ __forceinline__ void conv_w_item(const float* __restrict__ W,
                                            __half* __restrict__ dst, int t, int N, int K_IN) {
    const int SEGS = K_IN >> 3;
    int s8 = t % SEGS;
    int n = (t / SEGS) % N;
    int e = t / (N * SEGS);
    int i = s8 * 8;
    const float* src = W + ((size_t)e * N + n) * K_IN + i;
    float4 v0 = *(const float4*)src;
    float4 v1 = *(const float4*)(src + 4);
    uint4 H;
    H.x = pkh2(v0.x, v0.y);
    H.y = pkh2(v0.z, v0.w);
    H.z = pkh2(v1.x, v1.y);
    H.w = pkh2(v1.z, v1.w);
    int kg = e * K_IN + i;
    int chunk = kg >> 5, seg = (kg >> 3) & 3;
    size_t off = (size_t)chunk * ((size_t)N * 64) + SWZ(n, seg);  // bytes
    *(uint4*)((char*)dst + off) = H;
}

__global__ void convall(const float* __restrict__ x, const float* __restrict__ W0,
                        const float* __restrict__ W1, const float* __restrict__ W2,
                        __half* __restrict__ Ah, __half* __restrict__ wh) {
    int idx = blockIdx.x * blockDim.x + threadIdx.x;
    if (idx < 262144) {
        // ---- xconv: (4096,512) fp32 -> pre-swizzled fp16 plane ----
        int b = idx >> 6, s8 = idx & 63;
        int i = s8 * 8;
        const float* src = x + (size_t)b * 512 + i;
        float4 v0 = *(const float4*)src;
        float4 v1 = *(const float4*)(src + 4);
        uint4 H;
        H.x = pkh2(v0.x, v0.y);
        H.y = pkh2(v0.z, v0.w);
        H.z = pkh2(v1.x, v1.y);
        H.w = pkh2(v1.z, v1.w);
        int chunk = i >> 5, seg = (i >> 3) & 3;
        size_t off = (size_t)chunk * (4096 * 64) + SWZ(b, seg);
        *(uint4*)((char*)Ah + off) = H;
    } else if (idx < 262144 + 524288) {
        conv_w_item(W0, wh, idx - 262144, 1024, 512);
    } else if (idx < 262144 + 524288 + 1048576) {
        conv_w_item(W1, wh + 4194304, idx - (262144 + 524288), 1024, 1024);
    } else if (idx < 262144 + 524288 + 1048576 + 524288) {
        conv_w_item(W2, wh + 12582912, idx - (262144 + 524288 + 1048576), 512, 1024);
    }
}

// ---------------- GEMM: C(4096,N) = [blend ⊙ h](4096, 8*K_IN) x W^T ------------------------
// A plane is UNDUPLICATED plain-fp16 h. Blend applied via telescoping accumulator rescale:
// before expert e (e>=1): acc *= bl[e-1]/bl[e]; after loop: acc *= bl[7]. Exact fp32 blend.
// CTA tile MT x NT x 32; 8 warps (MT/32 x ...); 4-stage cp.async.bulk ring.
// OUTMODE: 0 = fp32 row-major out, 1 = fp16 pre-swizzled chunk-major plane (next layer).
template <int MT, int NT, int K_IN, int N, int OUTMODE, bool DO_ELU>
__global__ __launch_bounds__(256, 2) void gemm_mma(
    const __half* __restrict__ Ah, const __half* __restrict__ Wh,
    const float* __restrict__ blend, const float* __restrict__ Bias,
    void* __restrict__ outp) {
    constexpr int CPE = K_IN / 32;     // chunks per expert
    constexpr int NC = 8 * CPE;        // total chunks
    constexpr int NST = 4;
    constexpr int AB = MT * 64;        // bytes: A tile
    constexpr int BB = NT * 64;        // bytes: B tile
    constexpr int STG = AB + BB;
    constexpr int MB_OFF = NST * STG;  // full[s] at +8s, empty[s] at +8*NST+8s
    constexpr int RT_OFF = MB_OFF + 128;  // fp32 ratio table [MT][8]
    constexpr int MW = MT / 32;        // warps along M
    constexpr int WNC = NT * MW / 8;   // warp N extent
    constexpr int NP = WNC / 16;
    constexpr int NTT = WNC / 8;
    constexpr size_t CHA = 4096 * 64;
    constexpr size_t CHB = (size_t)N * 64;

    extern __shared__ __align__(1024) char smem[];
    const uint32_t sb = smem_u32(smem);
    const int tid = threadIdx.x, wid = tid >> 5, lid = tid & 31;
    const int wm = wid % MW, wn = wid / MW;
    const int mBase = blockIdx.y * MT, nBase = blockIdx.x * NT;

    const uint32_t fullb = sb + MB_OFF;
    const uint32_t emptyb = sb + MB_OFF + 8 * NST;
    float* rtS = (float*)(smem + RT_OFF);

    if (tid == 0) {
#pragma unroll
        for (int s = 0; s < NST; s++) {
            MBAR_INIT(fullb + 8 * s, 1);
            MBAR_INIT(emptyb + 8 * s, 8);
        }
        FENCE_ASYNC();
    }
    // ratio table: rtS[r*8+e] = bl'[e-1]/bl'[e] (e>=1); rtS[r*8+0] = bl'[7] (final scale)
    for (int i = tid; i < MT * 8; i += 256) {
        int r = i >> 3, e = i & 7;
        const float* bl = blend + (size_t)(mBase + r) * 8;
        float v;
        if (e == 0) {
            v = fmaxf(bl[7], 1e-30f);
        } else {
            v = fmaxf(bl[e - 1], 1e-30f) / fmaxf(bl[e], 1e-30f);
        }
        rtS[i] = v;
    }
    __syncthreads();

    auto issue = [&](int s, int c) {
        const uint32_t st = sb + s * STG;
        const uint32_t mb = fullb + 8 * s;
        MBAR_EXPECT(mb, STG);
        CP_BULK(st, (const char*)Ah + (size_t)(c & (CPE - 1)) * CHA + (size_t)mBase * 64, AB, mb);
        CP_BULK(st + AB, (const char*)Wh + (size_t)c * CHB + (size_t)nBase * 64, BB, mb);
    };

    if (tid == 0) {
#pragma unroll
        for (int s = 0; s < NST; s++) issue(s, s);
    }

    float acc[2][NTT][4];
#pragma unroll
    for (int a = 0; a < 2; a++)
#pragma unroll
        for (int b = 0; b < NTT; b++)
#pragma unroll
            for (int c = 0; c < 4; c++) acc[a][b][c] = 0.f;

    const int rl0 = (lid >> 2);  // base row-in-tile component

    for (int c = 0; c < NC; c++) {
        // expert boundary: rescale accumulators by bl[e-1]/bl[e] (per row, fp32)
        if (c > 0 && (c & (CPE - 1)) == 0) {
            const int e = c / CPE;
#pragma unroll
            for (int mt = 0; mt < 2; mt++)
#pragma unroll
                for (int h = 0; h < 2; h++) {
                    int rloc = wm * 32 + mt * 16 + rl0 + h * 8;
                    float f = rtS[rloc * 8 + e];
#pragma unroll
                    for (int nt = 0; nt < NTT; nt++) {
                        acc[mt][nt][h * 2 + 0] *= f;
                        acc[mt][nt][h * 2 + 1] *= f;
                    }
                }
        }
        const int s = c % NST;
        const int r = c / NST;
        MBAR_WAIT(fullb + 8 * s, r & 1);

        const uint32_t aB = sb + s * STG;
        const uint32_t bB = aB + AB;
        const int mat = lid >> 3, ri = lid & 7;
#pragma unroll
        for (int kk = 0; kk < 2; kk++) {
            uint32_t bh[NP][4];
#pragma unroll
            for (int p = 0; p < NP; p++) {
                int n = wn * WNC + p * 16 + ((mat >> 1) << 3) + ri;
                int seg = kk * 2 + (mat & 1);
                ldsm4(bh[p][0], bh[p][1], bh[p][2], bh[p][3], bB + SWZ(n, seg));
            }
#pragma unroll
            for (int mt = 0; mt < 2; mt++) {
                uint32_t ah[4];
                int r2 = wm * 32 + mt * 16 + ((mat & 1) << 3) + ri;
                int seg = kk * 2 + (mat >> 1);
                ldsm4(ah[0], ah[1], ah[2], ah[3], aB + SWZ(r2, seg));
#pragma unroll
                for (int nt = 0; nt < NTT; nt++) {
                    mma16816(acc[mt][nt], ah, &bh[nt >> 1][(nt & 1) * 2]);
                }
            }
        }
        if (lid == 0) MBAR_ARRIVE(emptyb + 8 * s);
        if (tid == 0) {
            int cc = c + NST;
            if (cc < NC) {
                MBAR_WAIT(emptyb + 8 * s, r & 1);
                issue(s, cc);
            }
        }
    }

    // final telescoping scale: acc *= bl'[7]
#pragma unroll
    for (int mt = 0; mt < 2; mt++)
#pragma unroll
        for (int h = 0; h < 2; h++) {
            int rloc = wm * 32 + mt * 16 + rl0 + h * 8;
            float f = rtS[rloc * 8 + 0];
#pragma unroll
            for (int nt = 0; nt < NTT; nt++) {
                acc[mt][nt][h * 2 + 0] *= f;
                acc[mt][nt][h * 2 + 1] *= f;
            }
        }

    __syncthreads();  // all warps out of mainloop; stage smem now dead

    // ---- epilogue: blended bias + optional ELU ----
    float* biasS = (float*)smem;  // reuse stage region
    for (int i = tid; i < 8 * NT; i += 256)
        biasS[i] = Bias[(i / NT) * N + nBase + (i % NT)];
    __syncthreads();

#pragma unroll
    for (int mt = 0; mt < 2; mt++) {
#pragma unroll
        for (int hh = 0; hh < 2; hh++) {
            const int row = mBase + wm * 32 + mt * 16 + rl0 + hh * 8;
            float4 b0 = *(const float4*)(blend + (size_t)row * 8);
            float4 b1 = *(const float4*)(blend + (size_t)row * 8 + 4);
            float blv[8] = {b0.x, b0.y, b0.z, b0.w, b1.x, b1.y, b1.z, b1.w};
#pragma unroll
            for (int nt = 0; nt < NTT; nt++) {
                int cl = wn * WNC + nt * 8 + (lid & 3) * 2;  // tile-local col
                int col = nBase + cl;                        // global col
                float v0 = acc[mt][nt][hh * 2 + 0];
                float v1 = acc[mt][nt][hh * 2 + 1];
                float bb0 = 0.f, bb1 = 0.f;
#pragma unroll
                for (int e = 0; e < 8; e++) {
                    bb0 += blv[e] * biasS[e * NT + cl];
                    bb1 += blv[e] * biasS[e * NT + cl + 1];
                }
                v0 += bb0;
                v1 += bb1;
                if (DO_ELU) {
                    v0 = (v0 > 0.f) ? v0 : expm1f(v0);
                    v1 = (v1 > 0.f) ? v1 : expm1f(v1);
                }
                if (OUTMODE == 1) {
                    // write fp16 h directly in pre-swizzled chunk-major plane layout
                    size_t off = (size_t)(col >> 5) * CHA +
                                 (uint32_t)(SWZ(row, (col >> 3) & 3) + (col & 7) * 2);
                    *(uint32_t*)((char*)outp + off) = pkh2(v0, v1);
                } else {
                    *(float2*)((float*)outp + (size_t)row * N + col) = make_float2(v0, v1);
                }
            }
        }
    }
}

// ---------------- host ----------------
extern "C" void kernel_launch(void* const* d_in, const int* in_sizes, int n_in,
                              void* d_out, int out_size) {
    const float* blend = (const float*)d_in[0];  // (4096, 8)
    const float* x     = (const float*)d_in[1];  // (4096, 512)
    const float* W0    = (const float*)d_in[2];  // (8, 1024, 512)
    const float* B0    = (const float*)d_in[3];
    const float* W1    = (const float*)d_in[4];  // (8, 1024, 1024)
    const float* B1    = (const float*)d_in[5];
    const float* W2    = (const float*)d_in[6];  // (8, 512, 1024)
    const float* B2    = (const float*)d_in[7];
    float* out = (float*)d_out;                  // (4096, 512)

    __half *ax, *h1, *h2, *wh;
    cudaGetSymbolAddress((void**)&ax, g_X);
    cudaGetSymbolAddress((void**)&h1, g_H1);
    cudaGetSymbolAddress((void**)&h2, g_H2);
    cudaGetSymbolAddress((void**)&wh, g_Wh);

    // single fused convert: x + W0 + W1 + W2 -> pre-swizzled fp16 planes
    constexpr int CITEMS = 262144 + 524288 + 1048576 + 524288;  // 2359296
    convall<<<(CITEMS + 255) / 256, 256>>>(x, W0, W1, W2, ax, wh);

    // layers 0/1: CTA 128x128, 4 stages (64KB) + mbar + 4KB ratio table
    constexpr int S_L01 = 4 * (128 * 64 + 128 * 64) + 128 + 128 * 8 * 4;  // ~68.2KB
    // layer 2: CTA 64x128 (48KB stages) + mbar + 2KB ratio table
    constexpr int S_L2 = 4 * (64 * 64 + 128 * 64) + 128 + 64 * 8 * 4;     // ~50.2KB
    cudaFuncSetAttribute(gemm_mma<128, 128, 512, 1024, 1, true>,
                         cudaFuncAttributeMaxDynamicSharedMemorySize, S_L01);
    cudaFuncSetAttribute(gemm_mma<128, 128, 1024, 1024, 1, true>,
                         cudaFuncAttributeMaxDynamicSharedMemorySize, S_L01);
    cudaFuncSetAttribute(gemm_mma<64, 128, 1024, 512, 0, false>,
                         cudaFuncAttributeMaxDynamicSharedMemorySize, S_L2);

    // layer 0: x plane -> h1 plane (pre-swizzled fp16), ELU
    gemm_mma<128, 128, 512, 1024, 1, true><<<dim3(8, 32), 256, S_L01>>>(
        ax, wh, blend, B0, h1);
    // layer 1: h1 plane -> h2 plane, ELU
    gemm_mma<128, 128, 1024, 1024, 1, true><<<dim3(8, 32), 256, S_L01>>>(
        h1, wh + 4194304, blend, B1, h2);
    // layer 2: h2 plane -> fp32 out, linear
    gemm_mma<64, 128, 1024, 512, 0, false><<<dim3(4, 64), 256, S_L2>>>(
        h2, wh + 12582912, blend, B2, out);
}